// round 3
// baseline (speedup 1.0000x reference)
#include <cuda_runtime.h>
#include <math.h>

// Problem constants
#define BATCH 32
#define CIN   256
#define HH    32
#define WW    32
#define HW    1024                  // 32*32
#define NTOT  32768                 // BATCH*HW
#define K9    2304                  // 9*256
#define K25   6400                  // 25*256
#define OFFCH 50

// ---------------- scratch (static device globals; no allocation) ------------
__device__ float g_SA[(size_t)K9  * NTOT];   // 302 MB  im2col(x) / im2col(out)
__device__ float g_SB[(size_t)K25 * NTOT];   // 839 MB  deform-sampled im2col
__device__ float g_out[(size_t)BATCH * 256 * HW];   // intermediate "out"
__device__ float g_offb[(size_t)BATCH * OFFCH * HW];
__device__ float g_w1r[256 * K9];
__device__ float g_wor[OFFCH * K9];
__device__ float g_w3r[256 * K25];
__device__ float g_w2r[256 * K9];
__device__ float g_bn[6 * 256];   // scale1,shift1,scale3,shift3,scale2,shift2

// ---------------- BN param prep --------------------------------------------
__global__ void prep_bn(const float* __restrict__ g1, const float* __restrict__ b1,
                        const float* __restrict__ m1, const float* __restrict__ v1,
                        const float* __restrict__ g3, const float* __restrict__ b3,
                        const float* __restrict__ m3, const float* __restrict__ v3,
                        const float* __restrict__ g2, const float* __restrict__ b2,
                        const float* __restrict__ m2, const float* __restrict__ v2) {
    int i = threadIdx.x;
    if (i >= 256) return;
    float s1 = g1[i] * rsqrtf(v1[i] + 1e-5f);
    g_bn[i]        = s1;
    g_bn[256 + i]  = b1[i] - m1[i] * s1;
    float s3 = g3[i] * rsqrtf(v3[i] + 1e-5f);
    g_bn[512 + i]  = s3;
    g_bn[768 + i]  = b3[i] - m3[i] * s3;
    float s2 = g2[i] * rsqrtf(v2[i] + 1e-5f);
    g_bn[1024 + i] = s2;
    g_bn[1280 + i] = b2[i] - m2[i] * s2;
}

// ---------------- weight reorder:  w[O][C][T] -> wr[O][T*C + ...] -----------
// wr[o][t*256 + c] = w[o][c][t]
__global__ void reorder_w(const float* __restrict__ w, float* __restrict__ wr,
                          int O, int T) {
    int idx = blockIdx.x * blockDim.x + threadIdx.x;
    int total = O * 256 * T;
    if (idx >= total) return;
    int t = idx % T;
    int c = (idx / T) % 256;
    int o = idx / (T * 256);
    wr[(size_t)o * (256 * T) + t * 256 + c] = w[idx];
}

// ---------------- im2col for 3x3 pad1 ---------------------------------------
// S[(t*256+c)][b*1024+p] = in[b][c][ho-1+i][wo-1+j]   (zero pad)
__global__ void im2col3(const float* __restrict__ in, float* __restrict__ S) {
    int idx = blockIdx.x * blockDim.x + threadIdx.x;   // < 32*9*1024
    if (idx >= BATCH * 9 * HW) return;
    int p = idx & 1023;
    int t = (idx >> 10) % 9;
    int b = idx / (9 * HW);
    int ho = p >> 5, wo = p & 31;
    int i = t / 3, j = t % 3;
    int y = ho - 1 + i;
    int x = wo - 1 + j;
    bool valid = ((unsigned)y < 32u) && ((unsigned)x < 32u);
    const float* src = in + (size_t)b * (256 * HW) + y * 32 + x;
    float* Sp = S + (size_t)(t * 256) * NTOT + b * HW + p;
    #pragma unroll 4
    for (int c = 0; c < 256; c++) {
        float v = valid ? src[(size_t)c * HW] : 0.f;
        Sp[(size_t)c * NTOT] = v;
    }
}

// ---------------- deformable bilinear sampler -------------------------------
// S[(k*256+c)][b*1024+p] = bilinear(x[b][c], py, px) with zero outside borders
__global__ void sampler(const float* __restrict__ x, const float* __restrict__ off,
                        float* __restrict__ S) {
    int idx = blockIdx.x * blockDim.x + threadIdx.x;   // < 32*25*1024
    if (idx >= BATCH * 25 * HW) return;
    int p = idx & 1023;
    int k = (idx >> 10) % 25;
    int b = idx / (25 * HW);
    int ho = p >> 5, wo = p & 31;
    int i = k / 5, j = k % 5;
    const float* ob = off + (size_t)b * (OFFCH * HW);
    float dy = ob[(2 * k) * HW + p];
    float dx = ob[(2 * k + 1) * HW + p];
    float py = (float)(ho - 2 + i) + dy;
    float px = (float)(wo - 2 + j) + dx;
    float y0f = floorf(py), x0f = floorf(px);
    float wy1 = py - y0f, wx1 = px - x0f;
    float wy0 = 1.f - wy1, wx0 = 1.f - wx1;
    int y0 = (int)y0f, x0 = (int)x0f;
    int y1 = y0 + 1, x1 = x0 + 1;
    bool vy0 = ((unsigned)y0 < 32u), vy1 = ((unsigned)y1 < 32u);
    bool vx0 = ((unsigned)x0 < 32u), vx1 = ((unsigned)x1 < 32u);
    float w00 = (vy0 && vx0) ? wy0 * wx0 : 0.f;
    float w01 = (vy0 && vx1) ? wy0 * wx1 : 0.f;
    float w10 = (vy1 && vx0) ? wy1 * wx0 : 0.f;
    float w11 = (vy1 && vx1) ? wy1 * wx1 : 0.f;
    int cy0 = min(max(y0, 0), 31), cy1 = min(max(y1, 0), 31);
    int cx0 = min(max(x0, 0), 31), cx1 = min(max(x1, 0), 31);
    int a00 = cy0 * 32 + cx0, a01 = cy0 * 32 + cx1;
    int a10 = cy1 * 32 + cx0, a11 = cy1 * 32 + cx1;
    const float* xb = x + (size_t)b * (256 * HW);
    float* Sp = S + (size_t)(k * 256) * NTOT + b * HW + p;
    #pragma unroll 4
    for (int c = 0; c < 256; c++) {
        const float* xc = xb + (size_t)c * HW;
        float s = w00 * xc[a00] + w01 * xc[a01] + w10 * xc[a10] + w11 * xc[a11];
        Sp[(size_t)c * NTOT] = s;
    }
}

// ---------------- SGEMM  out[M, 32768] = A[M,K] * B[K,32768] + epilogue -----
// modes: 0 conv1: relu(bn)->out  | 1 offset: +bias->off buffer
//        2 deform: relu(bn)+aux->out | 3 conv2: relu(bn+aux)->out
#define BM 128
#define BN 128
#define BK 16
__global__ __launch_bounds__(256, 1)
void gemm_kernel(const float* __restrict__ A, const float* __restrict__ B,
                 int M, int K, int mode,
                 const float* __restrict__ scale, const float* __restrict__ shift,
                 const float* __restrict__ aux, float* __restrict__ out) {
    __shared__ float As[BK][BM + 4];
    __shared__ float Bs[BK][BN + 4];

    int tid = threadIdx.x;
    int tx = tid & 15;         // N direction (8 cols each)
    int ty = tid >> 4;         // M direction (8 rows each)
    int m0 = blockIdx.y * BM;
    int n0 = blockIdx.x * BN;

    float acc[8][8];
    #pragma unroll
    for (int i = 0; i < 8; i++)
        #pragma unroll
        for (int j = 0; j < 8; j++) acc[i][j] = 0.f;

    int arow = tid >> 2;            // 0..63
    int acol = (tid & 3) * 4;       // 0,4,8,12
    int brow = tid >> 5;            // 0..7
    int bcol = (tid & 31) * 4;      // 0..124

    for (int k0 = 0; k0 < K; k0 += BK) {
        // load A tile (transposed into As[k][m]); guard rows >= M
        #pragma unroll
        for (int r = 0; r < 2; r++) {
            int m = m0 + arow + r * 64;
            float4 v = make_float4(0.f, 0.f, 0.f, 0.f);
            if (m < M) v = *(const float4*)&A[(size_t)m * K + k0 + acol];
            As[acol + 0][arow + r * 64] = v.x;
            As[acol + 1][arow + r * 64] = v.y;
            As[acol + 2][arow + r * 64] = v.z;
            As[acol + 3][arow + r * 64] = v.w;
        }
        // load B tile
        #pragma unroll
        for (int r = 0; r < 2; r++) {
            float4 v = *(const float4*)&B[(size_t)(k0 + brow + r * 8) * NTOT + n0 + bcol];
            *(float4*)&Bs[brow + r * 8][bcol] = v;
        }
        __syncthreads();

        #pragma unroll
        for (int kk = 0; kk < BK; kk++) {
            float a[8], bb[8];
            *(float4*)&a[0]  = *(float4*)&As[kk][ty * 8];
            *(float4*)&a[4]  = *(float4*)&As[kk][ty * 8 + 4];
            *(float4*)&bb[0] = *(float4*)&Bs[kk][tx * 8];
            *(float4*)&bb[4] = *(float4*)&Bs[kk][tx * 8 + 4];
            #pragma unroll
            for (int i = 0; i < 8; i++)
                #pragma unroll
                for (int j = 0; j < 8; j++)
                    acc[i][j] = fmaf(a[i], bb[j], acc[i][j]);
        }
        __syncthreads();
    }

    // epilogue — each 128-col tile stays within one batch image (1024 % 128 == 0)
    int colbase = n0 + tx * 8;
    int bimg = colbase >> 10;
    int pbase = colbase & 1023;
    #pragma unroll
    for (int i = 0; i < 8; i++) {
        int row = m0 + ty * 8 + i;
        if (row >= M) continue;
        if (mode == 1) {
            float bias = shift[row];
            size_t base = (size_t)bimg * (OFFCH * HW) + (size_t)row * HW + pbase;
            #pragma unroll
            for (int j = 0; j < 8; j++) out[base + j] = acc[i][j] + bias;
        } else {
            float sc = scale[row], sh = shift[row];
            size_t base = (size_t)bimg * (256 * HW) + (size_t)row * HW + pbase;
            #pragma unroll
            for (int j = 0; j < 8; j++) {
                float v = fmaf(acc[i][j], sc, sh);
                if (mode == 0) {
                    out[base + j] = fmaxf(v, 0.f);
                } else if (mode == 2) {
                    out[base + j] = fmaxf(v, 0.f) + aux[base + j];
                } else { // mode 3
                    out[base + j] = fmaxf(v + aux[base + j], 0.f);
                }
            }
        }
    }
}

// ---------------- launcher ---------------------------------------------------
extern "C" void kernel_launch(void* const* d_in, const int* in_sizes, int n_in,
                              void* d_out, int out_size) {
    const float* x     = (const float*)d_in[0];
    const float* w1    = (const float*)d_in[1];
    const float* w_off = (const float*)d_in[2];
    const float* b_off = (const float*)d_in[3];
    const float* w3    = (const float*)d_in[4];
    const float* w2    = (const float*)d_in[5];
    const float* g1 = (const float*)d_in[6],  *b1 = (const float*)d_in[7];
    const float* m1 = (const float*)d_in[8],  *v1 = (const float*)d_in[9];
    const float* g3 = (const float*)d_in[10], *b3 = (const float*)d_in[11];
    const float* m3 = (const float*)d_in[12], *v3 = (const float*)d_in[13];
    const float* g2 = (const float*)d_in[14], *b2 = (const float*)d_in[15];
    const float* m2 = (const float*)d_in[16], *v2 = (const float*)d_in[17];
    float* out = (float*)d_out;

    float *sa, *sb, *gout, *goff, *w1r, *wor, *w3r, *w2r, *bn;
    cudaGetSymbolAddress((void**)&sa,   g_SA);
    cudaGetSymbolAddress((void**)&sb,   g_SB);
    cudaGetSymbolAddress((void**)&gout, g_out);
    cudaGetSymbolAddress((void**)&goff, g_offb);
    cudaGetSymbolAddress((void**)&w1r,  g_w1r);
    cudaGetSymbolAddress((void**)&wor,  g_wor);
    cudaGetSymbolAddress((void**)&w3r,  g_w3r);
    cudaGetSymbolAddress((void**)&w2r,  g_w2r);
    cudaGetSymbolAddress((void**)&bn,   g_bn);

    prep_bn<<<1, 256>>>(g1, b1, m1, v1, g3, b3, m3, v3, g2, b2, m2, v2);

    reorder_w<<<(256 * 256 * 9 + 255) / 256, 256>>>(w1, w1r, 256, 9);
    reorder_w<<<(OFFCH * 256 * 9 + 255) / 256, 256>>>(w_off, wor, OFFCH, 9);
    reorder_w<<<(256 * 256 * 25 + 255) / 256, 256>>>(w3, w3r, 256, 25);
    reorder_w<<<(256 * 256 * 9 + 255) / 256, 256>>>(w2, w2r, 256, 9);

    // im2col(x) -> S_A
    im2col3<<<(BATCH * 9 * HW) / 256, 256>>>(x, sa);

    // conv1: relu(bn1(w1 * S_A)) -> g_out
    gemm_kernel<<<dim3(NTOT / BN, 2), 256>>>(w1r, sa, 256, K9, 0,
                                             bn + 0, bn + 256, nullptr, gout);
    // offset conv: w_off * S_A + b_off -> g_offb
    gemm_kernel<<<dim3(NTOT / BN, 1), 256>>>(wor, sa, OFFCH, K9, 1,
                                             nullptr, b_off, nullptr, goff);
    // deformable sampling -> S_B
    sampler<<<(BATCH * 25 * HW) / 256, 256>>>(x, goff, sb);

    // deform conv: g_out += relu(bn3(w3 * S_B))
    gemm_kernel<<<dim3(NTOT / BN, 2), 256>>>(w3r, sb, 256, K25, 2,
                                             bn + 512, bn + 768, gout, gout);

    // im2col(g_out) -> S_A (reuse)
    im2col3<<<(BATCH * 9 * HW) / 256, 256>>>(gout, sa);

    // conv2: relu(bn2(w2 * S_A) + x) -> d_out
    gemm_kernel<<<dim3(NTOT / BN, 2), 256>>>(w2r, sa, 256, K9, 3,
                                             bn + 1024, bn + 1280, x, out);
}

// round 5
// speedup vs baseline: 2.1021x; 2.1021x over previous
#include <cuda_runtime.h>
#include <cuda_fp16.h>
#include <math.h>

#define BATCH 32
#define HW    1024
#define NTOT  32768
#define KCA   2304            // 9*256
#define KCB   6400            // 25*256

// ---------------- scratch ----------------
__device__ __half g_SAh[(size_t)NTOT * KCA];
__device__ __half g_SAl[(size_t)NTOT * KCA];
__device__ __half g_SBh[(size_t)NTOT * KCB];
__device__ __half g_SBl[(size_t)NTOT * KCB];
__device__ float g_xT [(size_t)BATCH * HW * 256];
__device__ float g_out[(size_t)BATCH * 256 * HW];
__device__ float g_offb[(size_t)BATCH * 50 * HW];
__device__ __half g_w1h[(size_t)256 * KCA], g_w1l[(size_t)256 * KCA];
__device__ __half g_woh[(size_t)128 * KCA], g_wol[(size_t)128 * KCA];
__device__ __half g_w3h[(size_t)256 * KCB], g_w3l[(size_t)256 * KCB];
__device__ __half g_w2h[(size_t)256 * KCA], g_w2l[(size_t)256 * KCA];
__device__ float g_bn[6 * 256];

// ---------------- helpers ----------------
__device__ __forceinline__ unsigned s2u(const void* p) {
    unsigned a;
    asm("{ .reg .u64 t; cvta.to.shared.u64 t, %1; cvt.u32.u64 %0, t; }" : "=r"(a) : "l"(p));
    return a;
}
__device__ __forceinline__ void hilo8h(const float* v, uint4& H, uint4& L) {
    unsigned h[4], l[4];
#pragma unroll
    for (int i = 0; i < 4; i++) {
        float a = v[2 * i], b = v[2 * i + 1];
        __half ha = __float2half_rn(a), hb = __float2half_rn(b);
        __half2 hp = __halves2half2(ha, hb);
        __half2 lp = __halves2half2(__float2half_rn(a - __half2float(ha)),
                                    __float2half_rn(b - __half2float(hb)));
        h[i] = *(unsigned*)&hp; l[i] = *(unsigned*)&lp;
    }
    H = make_uint4(h[0], h[1], h[2], h[3]);
    L = make_uint4(l[0], l[1], l[2], l[3]);
}

// ---------------- prep kernels ----------------
__global__ void prep_bn(const float* g1, const float* b1, const float* m1, const float* v1,
                        const float* g3, const float* b3, const float* m3, const float* v3,
                        const float* g2, const float* b2, const float* m2, const float* v2) {
    int i = threadIdx.x;
    float s1 = g1[i] * rsqrtf(v1[i] + 1e-5f);
    g_bn[i] = s1;          g_bn[256 + i] = b1[i] - m1[i] * s1;
    float s3 = g3[i] * rsqrtf(v3[i] + 1e-5f);
    g_bn[512 + i] = s3;    g_bn[768 + i] = b3[i] - m3[i] * s3;
    float s2 = g2[i] * rsqrtf(v2[i] + 1e-5f);
    g_bn[1024 + i] = s2;   g_bn[1280 + i] = b2[i] - m2[i] * s2;
}

// w[O][256][T] -> Wh/Wl[o][t*256+c] (rows o>=Ov zero-padded)
__global__ void reorder_w_f16(const float* __restrict__ w, __half* __restrict__ Wh,
                              __half* __restrict__ Wl, int Ov, int T) {
    int idx = blockIdx.x * 256 + threadIdx.x;
    int c = idx & 255;
    int t = (idx >> 8) % T;
    int o = idx / (256 * T);
    float v = (o < Ov) ? w[((size_t)(o * 256 + c)) * T + t] : 0.f;
    __half h = __float2half_rn(v);
    __half l = __float2half_rn(v - __half2float(h));
    size_t a = (size_t)o * (T * 256) + t * 256 + c;
    Wh[a] = h; Wl[a] = l;
}

__global__ void transpose_cl(const float* __restrict__ in, float* __restrict__ out) {
    __shared__ float tile[32][33];
    int b = blockIdx.z, c0 = blockIdx.y * 32, p0 = blockIdx.x * 32;
    int tx = threadIdx.x, ty = threadIdx.y;
    const float* ib = in + ((size_t)b << 18);
#pragma unroll
    for (int i = 0; i < 32; i += 8)
        tile[ty + i][tx] = ib[(size_t)(c0 + ty + i) * 1024 + p0 + tx];
    __syncthreads();
    float* ob = out + ((size_t)b << 18);
#pragma unroll
    for (int i = 0; i < 32; i += 8)
        ob[(size_t)(p0 + ty + i) * 256 + c0 + tx] = tile[tx][ty + i];
}

// im2col 3x3 pad1: xT(NHWC fp32) -> Sh/Sl[n][k]
__global__ void im2col_f16(const float* __restrict__ xT, __half* __restrict__ Sh,
                           __half* __restrict__ Sl) {
    int idx = blockIdx.x * 256 + threadIdx.x;     // NTOT*9*32
    int c8 = idx & 31;
    int t  = (idx >> 5) % 9;
    int n  = idx / 288;
    int p = n & 1023, b = n >> 10;
    int y = (p >> 5) - 1 + t / 3;
    int x = (p & 31) - 1 + t % 3;
    float vs[8] = {0,0,0,0,0,0,0,0};
    if ((unsigned)y < 32u && (unsigned)x < 32u) {
        const float4* src = (const float4*)(xT + ((size_t)b << 18) + (size_t)(y * 32 + x) * 256 + c8 * 8);
        float4 a = src[0], q = src[1];
        vs[0]=a.x; vs[1]=a.y; vs[2]=a.z; vs[3]=a.w; vs[4]=q.x; vs[5]=q.y; vs[6]=q.z; vs[7]=q.w;
    }
    uint4 H, L; hilo8h(vs, H, L);
    size_t a = (size_t)n * KCA + t * 256 + c8 * 8;
    *(uint4*)(Sh + a) = H; *(uint4*)(Sl + a) = L;
}

__global__ void sampler_f16(const float* __restrict__ xT, const float* __restrict__ off,
                            __half* __restrict__ Sh, __half* __restrict__ Sl) {
    int idx = blockIdx.x * 256 + threadIdx.x;     // NTOT*25*32
    int c8 = idx & 31;
    int k  = (idx >> 5) % 25;
    int n  = idx / 800;
    int p = n & 1023, b = n >> 10;
    int ho = p >> 5, wo = p & 31;
    const float* ob = off + (size_t)b * (50 * 1024);
    float dy = ob[(2 * k) * 1024 + p];
    float dx = ob[(2 * k + 1) * 1024 + p];
    float py = (float)(ho - 2 + k / 5) + dy;
    float px = (float)(wo - 2 + k % 5) + dx;
    float y0f = floorf(py), x0f = floorf(px);
    float wy1 = py - y0f, wx1 = px - x0f;
    float wy0 = 1.f - wy1, wx0 = 1.f - wx1;
    int y0 = (int)y0f, x0 = (int)x0f, y1 = y0 + 1, x1 = x0 + 1;
    float w00 = ((unsigned)y0 < 32u && (unsigned)x0 < 32u) ? wy0 * wx0 : 0.f;
    float w01 = ((unsigned)y0 < 32u && (unsigned)x1 < 32u) ? wy0 * wx1 : 0.f;
    float w10 = ((unsigned)y1 < 32u && (unsigned)x0 < 32u) ? wy1 * wx0 : 0.f;
    float w11 = ((unsigned)y1 < 32u && (unsigned)x1 < 32u) ? wy1 * wx1 : 0.f;
    int cy0 = min(max(y0, 0), 31), cy1 = min(max(y1, 0), 31);
    int cx0 = min(max(x0, 0), 31), cx1 = min(max(x1, 0), 31);
    const float* xb = xT + ((size_t)b << 18);
    const float4* r00 = (const float4*)(xb + (size_t)(cy0 * 32 + cx0) * 256 + c8 * 8);
    const float4* r01 = (const float4*)(xb + (size_t)(cy0 * 32 + cx1) * 256 + c8 * 8);
    const float4* r10 = (const float4*)(xb + (size_t)(cy1 * 32 + cx0) * 256 + c8 * 8);
    const float4* r11 = (const float4*)(xb + (size_t)(cy1 * 32 + cx1) * 256 + c8 * 8);
    float vs[8];
#pragma unroll
    for (int q = 0; q < 2; q++) {
        float4 a = r00[q], c = r01[q], d = r10[q], e = r11[q];
        vs[q*4+0] = w00*a.x + w01*c.x + w10*d.x + w11*e.x;
        vs[q*4+1] = w00*a.y + w01*c.y + w10*d.y + w11*e.y;
        vs[q*4+2] = w00*a.z + w01*c.z + w10*d.z + w11*e.z;
        vs[q*4+3] = w00*a.w + w01*c.w + w10*d.w + w11*e.w;
    }
    uint4 H, L; hilo8h(vs, H, L);
    size_t a = (size_t)n * KCB + k * 256 + c8 * 8;
    *(uint4*)(Sh + a) = H; *(uint4*)(Sl + a) = L;
}

// ---------------- mma.sync GEMM ----------------
// C[row, n] = Wh·Sh + Wl·Sh + Wh·Sl  (fp32 accum), fused epilogue.
// modes: 0 relu(bn); 1 acc+bias rows<50 -> offsets; 2 aux+relu(bn); 3 relu(bn+aux)
#define TSLOT 10240                    // 128 rows * 80 bytes
#define GSMEM (8 * TSLOT)              // 4 tiles x 2 buffers

__device__ __forceinline__ void ldsm4(unsigned* r, unsigned a) {
    asm volatile("ldmatrix.sync.aligned.m8n8.x4.shared.b16 {%0,%1,%2,%3}, [%4];"
                 : "=r"(r[0]), "=r"(r[1]), "=r"(r[2]), "=r"(r[3]) : "r"(a));
}
__device__ __forceinline__ void ldsm2(unsigned* r, unsigned a) {
    asm volatile("ldmatrix.sync.aligned.m8n8.x2.shared.b16 {%0,%1}, [%2];"
                 : "=r"(r[0]), "=r"(r[1]) : "r"(a));
}
__device__ __forceinline__ void mmaf16(float* d, const unsigned* a, const unsigned* b) {
    asm volatile("mma.sync.aligned.m16n8k16.row.col.f32.f16.f16.f32 "
                 "{%0,%1,%2,%3}, {%4,%5,%6,%7}, {%8,%9}, {%0,%1,%2,%3};"
                 : "+f"(d[0]), "+f"(d[1]), "+f"(d[2]), "+f"(d[3])
                 : "r"(a[0]), "r"(a[1]), "r"(a[2]), "r"(a[3]), "r"(b[0]), "r"(b[1]));
}

__global__ __launch_bounds__(256, 1) void gemm_tc(
    const __half* __restrict__ Ah, const __half* __restrict__ Al,
    const __half* __restrict__ Bh, const __half* __restrict__ Bl,
    int Kc, int mode,
    const float* __restrict__ scale, const float* __restrict__ shift,
    const float* __restrict__ aux, float* __restrict__ outp)
{
    extern __shared__ char sm[];
    unsigned sb = s2u(sm);
    int tid = threadIdx.x, wid = tid >> 5, lane = tid & 31;
    int n0 = blockIdx.x * 128;
    int m0 = blockIdx.y * 128;

    float acc[4][4][4];
#pragma unroll
    for (int i = 0; i < 4; i++)
#pragma unroll
        for (int j = 0; j < 4; j++) {
            acc[i][j][0] = 0.f; acc[i][j][1] = 0.f; acc[i][j][2] = 0.f; acc[i][j][3] = 0.f;
        }

    const __half* gp[4] = {Ah, Al, Bh, Bl};
    int NSt = Kc >> 5;

    // prologue: stage 0 -> buf 0
    {
        int kk = 0;
        for (int u = tid; u < 2048; u += 256) {
            int tile = u >> 9, v = u & 511, row = v >> 2, ch = v & 3;
            int grow = (tile < 2) ? (m0 + row) : (n0 + row);
            const __half* g = gp[tile] + (size_t)grow * Kc + kk + ch * 8;
            unsigned sa = sb + (unsigned)(tile * 2) * TSLOT + row * 80 + ch * 16;
            asm volatile("cp.async.cg.shared.global [%0], [%1], 16;" :: "r"(sa), "l"(g));
        }
        asm volatile("cp.async.commit_group;");
    }

    int warpM = wid >> 2, warpN = wid & 3;
    for (int s = 0; s < NSt; s++) {
        int buf = s & 1;
        asm volatile("cp.async.wait_group 0;");
        __syncthreads();
        if (s + 1 < NSt) {
            int kk = (s + 1) << 5;
            for (int u = tid; u < 2048; u += 256) {
                int tile = u >> 9, v = u & 511, row = v >> 2, ch = v & 3;
                int grow = (tile < 2) ? (m0 + row) : (n0 + row);
                const __half* g = gp[tile] + (size_t)grow * Kc + kk + ch * 8;
                unsigned sa = sb + (unsigned)(tile * 2 + (buf ^ 1)) * TSLOT + row * 80 + ch * 16;
                asm volatile("cp.async.cg.shared.global [%0], [%1], 16;" :: "r"(sa), "l"(g));
            }
            asm volatile("cp.async.commit_group;");
        }
        unsigned bAh = sb + (unsigned)(0 * 2 + buf) * TSLOT;
        unsigned bAl = sb + (unsigned)(1 * 2 + buf) * TSLOT;
        unsigned bBh = sb + (unsigned)(2 * 2 + buf) * TSLOT;
        unsigned bBl = sb + (unsigned)(3 * 2 + buf) * TSLOT;
#pragma unroll
        for (int ks = 0; ks < 2; ks++) {
            unsigned kb = ks * 32;     // bytes within row for k0
            unsigned ah[4][4], al[4][4], bh[4][2], bl[4][2];
            unsigned aoff = (unsigned)(warpM * 64 + (lane & 15)) * 80 + kb + ((lane >> 4) * 16);
#pragma unroll
            for (int mi = 0; mi < 4; mi++) {
                ldsm4(ah[mi], bAh + aoff + mi * (16 * 80));
                ldsm4(al[mi], bAl + aoff + mi * (16 * 80));
            }
            unsigned boff = (unsigned)(warpN * 32 + (lane & 7)) * 80 + kb + (((lane >> 3) & 1) * 16);
#pragma unroll
            for (int ni = 0; ni < 4; ni++) {
                ldsm2(bh[ni], bBh + boff + ni * (8 * 80));
                ldsm2(bl[ni], bBl + boff + ni * (8 * 80));
            }
#pragma unroll
            for (int mi = 0; mi < 4; mi++)
#pragma unroll
                for (int ni = 0; ni < 4; ni++) {
                    mmaf16(acc[mi][ni], ah[mi], bh[ni]);
                    mmaf16(acc[mi][ni], al[mi], bh[ni]);
                    mmaf16(acc[mi][ni], ah[mi], bl[ni]);
                }
        }
        __syncthreads();
    }

    // epilogue
    int g = lane >> 2, cp2 = (lane & 3) * 2;
    int bimg = n0 >> 10;
    int pix0 = (n0 & 1023) + warpN * 32 + cp2;
#pragma unroll
    for (int mi = 0; mi < 4; mi++) {
#pragma unroll
        for (int h8 = 0; h8 < 2; h8++) {
            int row = m0 + warpM * 64 + mi * 16 + g + h8 * 8;
            if (mode == 1) {
                if (row < 50) {
                    float sh = shift[row];
                    float* dst = outp + ((size_t)bimg * 50 + row) * 1024;
#pragma unroll
                    for (int ni = 0; ni < 4; ni++) {
                        float2 v;
                        v.x = acc[mi][ni][h8 * 2 + 0] + sh;
                        v.y = acc[mi][ni][h8 * 2 + 1] + sh;
                        *(float2*)(dst + pix0 + ni * 8) = v;
                    }
                }
            } else {
                float sc = scale[row], sh = shift[row];
                size_t base = ((size_t)bimg * 256 + row) * 1024;
#pragma unroll
                for (int ni = 0; ni < 4; ni++) {
                    float2 v;
                    v.x = fmaf(acc[mi][ni][h8 * 2 + 0], sc, sh);
                    v.y = fmaf(acc[mi][ni][h8 * 2 + 1], sc, sh);
                    size_t o = base + pix0 + ni * 8;
                    if (mode == 0) {
                        v.x = fmaxf(v.x, 0.f); v.y = fmaxf(v.y, 0.f);
                    } else if (mode == 2) {
                        float2 a = *(const float2*)(aux + o);
                        v.x = fmaxf(v.x, 0.f) + a.x; v.y = fmaxf(v.y, 0.f) + a.y;
                    } else {
                        float2 a = *(const float2*)(aux + o);
                        v.x = fmaxf(v.x + a.x, 0.f); v.y = fmaxf(v.y + a.y, 0.f);
                    }
                    *(float2*)(outp + o) = v;
                }
            }
        }
    }
}

// ---------------- launcher ----------------
extern "C" void kernel_launch(void* const* d_in, const int* in_sizes, int n_in,
                              void* d_out, int out_size) {
    const float* x     = (const float*)d_in[0];
    const float* w1    = (const float*)d_in[1];
    const float* w_off = (const float*)d_in[2];
    const float* b_off = (const float*)d_in[3];
    const float* w3    = (const float*)d_in[4];
    const float* w2    = (const float*)d_in[5];
    const float* g1 = (const float*)d_in[6],  *b1 = (const float*)d_in[7];
    const float* m1 = (const float*)d_in[8],  *v1 = (const float*)d_in[9];
    const float* g3 = (const float*)d_in[10], *b3 = (const float*)d_in[11];
    const float* m3 = (const float*)d_in[12], *v3 = (const float*)d_in[13];
    const float* g2 = (const float*)d_in[14], *b2 = (const float*)d_in[15];
    const float* m2 = (const float*)d_in[16], *v2 = (const float*)d_in[17];
    float* out = (float*)d_out;

    cudaFuncSetAttribute(gemm_tc, cudaFuncAttributeMaxDynamicSharedMemorySize, GSMEM);

    __half *sah, *sal, *sbh, *sbl, *w1h, *w1l, *woh, *wol, *w3h, *w3l, *w2h, *w2l;
    float *xT, *gout, *goff, *bn;
    cudaGetSymbolAddress((void**)&sah, g_SAh);
    cudaGetSymbolAddress((void**)&sal, g_SAl);
    cudaGetSymbolAddress((void**)&sbh, g_SBh);
    cudaGetSymbolAddress((void**)&sbl, g_SBl);
    cudaGetSymbolAddress((void**)&xT,  g_xT);
    cudaGetSymbolAddress((void**)&gout, g_out);
    cudaGetSymbolAddress((void**)&goff, g_offb);
    cudaGetSymbolAddress((void**)&w1h, g_w1h);  cudaGetSymbolAddress((void**)&w1l, g_w1l);
    cudaGetSymbolAddress((void**)&woh, g_woh);  cudaGetSymbolAddress((void**)&wol, g_wol);
    cudaGetSymbolAddress((void**)&w3h, g_w3h);  cudaGetSymbolAddress((void**)&w3l, g_w3l);
    cudaGetSymbolAddress((void**)&w2h, g_w2h);  cudaGetSymbolAddress((void**)&w2l, g_w2l);
    cudaGetSymbolAddress((void**)&bn,  g_bn);

    prep_bn<<<1, 256>>>(g1, b1, m1, v1, g3, b3, m3, v3, g2, b2, m2, v2);
    reorder_w_f16<<<2304, 256>>>(w1, w1h, w1l, 256, 9);
    reorder_w_f16<<<1152, 256>>>(w_off, woh, wol, 50, 9);
    reorder_w_f16<<<6400, 256>>>(w3, w3h, w3l, 256, 25);
    reorder_w_f16<<<2304, 256>>>(w2, w2h, w2l, 256, 9);

    transpose_cl<<<dim3(32, 8, 32), dim3(32, 8)>>>(x, xT);
    im2col_f16<<<36864, 256>>>(xT, sah, sal);

    // conv1: relu(bn1) -> g_out
    gemm_tc<<<dim3(256, 2), 256, GSMEM>>>(w1h, w1l, sah, sal, KCA, 0, bn, bn + 256, nullptr, gout);
    // offset conv: + b_off -> g_offb
    gemm_tc<<<dim3(256, 1), 256, GSMEM>>>(woh, wol, sah, sal, KCA, 1, nullptr, b_off, nullptr, goff);
    // deformable sampling -> SB planes
    sampler_f16<<<102400, 256>>>(xT, goff, sbh, sbl);
    // deform conv: g_out += relu(bn3)
    gemm_tc<<<dim3(256, 2), 256, GSMEM>>>(w3h, w3l, sbh, sbl, KCB, 2, bn + 512, bn + 768, gout, gout);

    transpose_cl<<<dim3(32, 8, 32), dim3(32, 8)>>>(gout, xT);
    im2col_f16<<<36864, 256>>>(xT, sah, sal);
    // conv2: relu(bn2 + x) -> out
    gemm_tc<<<dim3(256, 2), 256, GSMEM>>>(w2h, w2l, sah, sal, KCA, 3, bn + 1024, bn + 1280, x, out);
}

// round 7
// speedup vs baseline: 3.0844x; 1.4673x over previous
#include <cuda_runtime.h>
#include <cuda_fp16.h>
#include <math.h>

#define BATCH 32
#define HW    1024
#define NTOT  32768
#define KCA   2304            // 9*256
#define KCB   6400            // 25*256

// ---------------- scratch ----------------
__device__ __half g_S[(size_t)NTOT * KCB];            // shared data plane (419 MB)
__device__ float g_xT [(size_t)BATCH * HW * 256];
__device__ float g_out[(size_t)BATCH * 256 * HW];
__device__ float g_offb[(size_t)BATCH * 50 * HW];
__device__ __half g_wch[(size_t)384 * KCA], g_wcl[(size_t)384 * KCA];  // conv1+offset fused
__device__ __half g_w3h[(size_t)256 * KCB], g_w3l[(size_t)256 * KCB];
__device__ __half g_w2h[(size_t)256 * KCA], g_w2l[(size_t)256 * KCA];
__device__ float g_bn[6 * 256];

// ---------------- helpers ----------------
__device__ __forceinline__ unsigned s2u(const void* p) {
    unsigned a;
    asm("{ .reg .u64 t; cvta.to.shared.u64 t, %1; cvt.u32.u64 %0, t; }" : "=r"(a) : "l"(p));
    return a;
}
__device__ __forceinline__ uint4 pack8h(const float* v) {
    unsigned r[4];
#pragma unroll
    for (int i = 0; i < 4; i++) {
        __half2 hp = __floats2half2_rn(v[2 * i], v[2 * i + 1]);
        r[i] = *(unsigned*)&hp;
    }
    return make_uint4(r[0], r[1], r[2], r[3]);
}

// ---------------- prep kernels ----------------
__global__ void prep_bn(const float* g1, const float* b1, const float* m1, const float* v1,
                        const float* g3, const float* b3, const float* m3, const float* v3,
                        const float* g2, const float* b2, const float* m2, const float* v2) {
    int i = threadIdx.x;
    float s1 = g1[i] * rsqrtf(v1[i] + 1e-5f);
    g_bn[i] = s1;          g_bn[256 + i] = b1[i] - m1[i] * s1;
    float s3 = g3[i] * rsqrtf(v3[i] + 1e-5f);
    g_bn[512 + i] = s3;    g_bn[768 + i] = b3[i] - m3[i] * s3;
    float s2 = g2[i] * rsqrtf(v2[i] + 1e-5f);
    g_bn[1024 + i] = s2;   g_bn[1280 + i] = b2[i] - m2[i] * s2;
}

// w[O][256][T] -> Wh/Wl[rowoff+o][t*256+c]  (o >= Ov zero-padded)
__global__ void reorder_w_f16(const float* __restrict__ w, __half* __restrict__ Wh,
                              __half* __restrict__ Wl, int Ov, int T, int rowoff) {
    int idx = blockIdx.x * 256 + threadIdx.x;
    int c = idx & 255;
    int t = (idx >> 8) % T;
    int o = idx / (256 * T);
    float v = (o < Ov) ? w[((size_t)(o * 256 + c)) * T + t] : 0.f;
    __half h = __float2half_rn(v);
    __half l = __float2half_rn(v - __half2float(h));
    size_t a = (size_t)(rowoff + o) * (T * 256) + t * 256 + c;
    Wh[a] = h; Wl[a] = l;
}

__global__ void transpose_cl(const float* __restrict__ in, float* __restrict__ out) {
    __shared__ float tile[32][33];
    int b = blockIdx.z, c0 = blockIdx.y * 32, p0 = blockIdx.x * 32;
    int tx = threadIdx.x, ty = threadIdx.y;
    const float* ib = in + ((size_t)b << 18);
#pragma unroll
    for (int i = 0; i < 32; i += 8)
        tile[ty + i][tx] = ib[(size_t)(c0 + ty + i) * 1024 + p0 + tx];
    __syncthreads();
    float* ob = out + ((size_t)b << 18);
#pragma unroll
    for (int i = 0; i < 32; i += 8)
        ob[(size_t)(p0 + ty + i) * 256 + c0 + tx] = tile[tx][ty + i];
}

// im2col 3x3 pad1: xT(NHWC fp32) -> S[n][k] fp16
__global__ void im2col_f16(const float* __restrict__ xT, __half* __restrict__ S) {
    int idx = blockIdx.x * 256 + threadIdx.x;     // NTOT*9*32
    int c8 = idx & 31;
    int t  = (idx >> 5) % 9;
    int n  = idx / 288;
    int p = n & 1023, b = n >> 10;
    int y = (p >> 5) - 1 + t / 3;
    int x = (p & 31) - 1 + t % 3;
    float vs[8] = {0,0,0,0,0,0,0,0};
    if ((unsigned)y < 32u && (unsigned)x < 32u) {
        const float4* src = (const float4*)(xT + ((size_t)b << 18) + (size_t)(y * 32 + x) * 256 + c8 * 8);
        float4 a = src[0], q = src[1];
        vs[0]=a.x; vs[1]=a.y; vs[2]=a.z; vs[3]=a.w; vs[4]=q.x; vs[5]=q.y; vs[6]=q.z; vs[7]=q.w;
    }
    *(uint4*)(S + (size_t)n * KCA + t * 256 + c8 * 8) = pack8h(vs);
}

__global__ void sampler_f16(const float* __restrict__ xT, const float* __restrict__ off,
                            __half* __restrict__ S) {
    int idx = blockIdx.x * 256 + threadIdx.x;     // NTOT*25*32
    int c8 = idx & 31;
    int k  = (idx >> 5) % 25;
    int n  = idx / 800;
    int p = n & 1023, b = n >> 10;
    int ho = p >> 5, wo = p & 31;
    const float* ob = off + (size_t)b * (50 * 1024);
    float dy = ob[(2 * k) * 1024 + p];
    float dx = ob[(2 * k + 1) * 1024 + p];
    float py = (float)(ho - 2 + k / 5) + dy;
    float px = (float)(wo - 2 + k % 5) + dx;
    float y0f = floorf(py), x0f = floorf(px);
    float wy1 = py - y0f, wx1 = px - x0f;
    float wy0 = 1.f - wy1, wx0 = 1.f - wx1;
    int y0 = (int)y0f, x0 = (int)x0f, y1 = y0 + 1, x1 = x0 + 1;
    float w00 = ((unsigned)y0 < 32u && (unsigned)x0 < 32u) ? wy0 * wx0 : 0.f;
    float w01 = ((unsigned)y0 < 32u && (unsigned)x1 < 32u) ? wy0 * wx1 : 0.f;
    float w10 = ((unsigned)y1 < 32u && (unsigned)x0 < 32u) ? wy1 * wx0 : 0.f;
    float w11 = ((unsigned)y1 < 32u && (unsigned)x1 < 32u) ? wy1 * wx1 : 0.f;
    int cy0 = min(max(y0, 0), 31), cy1 = min(max(y1, 0), 31);
    int cx0 = min(max(x0, 0), 31), cx1 = min(max(x1, 0), 31);
    const float* xb = xT + ((size_t)b << 18);
    const float4* r00 = (const float4*)(xb + (size_t)(cy0 * 32 + cx0) * 256 + c8 * 8);
    const float4* r01 = (const float4*)(xb + (size_t)(cy0 * 32 + cx1) * 256 + c8 * 8);
    const float4* r10 = (const float4*)(xb + (size_t)(cy1 * 32 + cx0) * 256 + c8 * 8);
    const float4* r11 = (const float4*)(xb + (size_t)(cy1 * 32 + cx1) * 256 + c8 * 8);
    float vs[8];
#pragma unroll
    for (int q = 0; q < 2; q++) {
        float4 a = r00[q], c = r01[q], d = r10[q], e = r11[q];
        vs[q*4+0] = w00*a.x + w01*c.x + w10*d.x + w11*e.x;
        vs[q*4+1] = w00*a.y + w01*c.y + w10*d.y + w11*e.y;
        vs[q*4+2] = w00*a.z + w01*c.z + w10*d.z + w11*e.z;
        vs[q*4+3] = w00*a.w + w01*c.w + w10*d.w + w11*e.w;
    }
    *(uint4*)(S + (size_t)n * KCB + k * 256 + c8 * 8) = pack8h(vs);
}

// ---------------- mma.sync GEMM: C = (Wh + Wl) · S, fused epilogue ----------
// mode 0: fused conv1+offset (rows<256: relu(bn)->outp; rows 256..305: +boff->offp)
// mode 2: outp = aux + relu(bn(C))      mode 3: outp = relu(bn(C) + aux)
#define TSLOT 10240                    // 128 rows * 80 bytes
#define GSMEM (6 * TSLOT)

__device__ __forceinline__ void ldsm4(unsigned* r, unsigned a) {
    asm volatile("ldmatrix.sync.aligned.m8n8.x4.shared.b16 {%0,%1,%2,%3}, [%4];"
                 : "=r"(r[0]), "=r"(r[1]), "=r"(r[2]), "=r"(r[3]) : "r"(a));
}
__device__ __forceinline__ void ldsm2(unsigned* r, unsigned a) {
    asm volatile("ldmatrix.sync.aligned.m8n8.x2.shared.b16 {%0,%1}, [%2];"
                 : "=r"(r[0]), "=r"(r[1]) : "r"(a));
}
__device__ __forceinline__ void mmaf16(float* d, const unsigned* a, const unsigned* b) {
    asm volatile("mma.sync.aligned.m16n8k16.row.col.f32.f16.f16.f32 "
                 "{%0,%1,%2,%3}, {%4,%5,%6,%7}, {%8,%9}, {%0,%1,%2,%3};"
                 : "+f"(d[0]), "+f"(d[1]), "+f"(d[2]), "+f"(d[3])
                 : "r"(a[0]), "r"(a[1]), "r"(a[2]), "r"(a[3]), "r"(b[0]), "r"(b[1]));
}

__global__ __launch_bounds__(256, 2) void gemm_tc(
    const __half* __restrict__ Wh, const __half* __restrict__ Wl,
    const __half* __restrict__ S, int Kc, int mode,
    const float* __restrict__ scale, const float* __restrict__ shift,
    const float* __restrict__ boff,
    const float* __restrict__ aux, float* __restrict__ outp, float* __restrict__ offp)
{
    extern __shared__ char sm[];
    unsigned sb = s2u(sm);
    int tid = threadIdx.x, wid = tid >> 5, lane = tid & 31;
    int m0 = blockIdx.x * 128;          // mtile (fast-varying => ntile shared in L2)
    int n0 = blockIdx.y * 128;

    float acc[4][4][4];
#pragma unroll
    for (int i = 0; i < 4; i++)
#pragma unroll
        for (int j = 0; j < 4; j++) {
            acc[i][j][0] = 0.f; acc[i][j][1] = 0.f; acc[i][j][2] = 0.f; acc[i][j][3] = 0.f;
        }

    const __half* gp[3] = {Wh, Wl, S};
    int NSt = Kc >> 5;

    // prologue
    for (int u = tid; u < 1536; u += 256) {
        int tile = u >> 9, v = u & 511, row = v >> 2, ch = v & 3;
        int grow = (tile < 2) ? (m0 + row) : (n0 + row);
        const __half* g = gp[tile] + (size_t)grow * Kc + ch * 8;
        unsigned sa = sb + (unsigned)(tile * 2) * TSLOT + row * 80 + ch * 16;
        asm volatile("cp.async.cg.shared.global [%0], [%1], 16;" :: "r"(sa), "l"(g));
    }
    asm volatile("cp.async.commit_group;");

    int warpM = wid >> 2, warpN = wid & 3;
    for (int s = 0; s < NSt; s++) {
        int buf = s & 1;
        asm volatile("cp.async.wait_group 0;");
        __syncthreads();
        if (s + 1 < NSt) {
            int kk = (s + 1) << 5;
            for (int u = tid; u < 1536; u += 256) {
                int tile = u >> 9, v = u & 511, row = v >> 2, ch = v & 3;
                int grow = (tile < 2) ? (m0 + row) : (n0 + row);
                const __half* g = gp[tile] + (size_t)grow * Kc + kk + ch * 8;
                unsigned sa = sb + (unsigned)(tile * 2 + (buf ^ 1)) * TSLOT + row * 80 + ch * 16;
                asm volatile("cp.async.cg.shared.global [%0], [%1], 16;" :: "r"(sa), "l"(g));
            }
            asm volatile("cp.async.commit_group;");
        }
        unsigned bW0 = sb + (unsigned)(0 * 2 + buf) * TSLOT;
        unsigned bW1 = sb + (unsigned)(1 * 2 + buf) * TSLOT;
        unsigned bS  = sb + (unsigned)(2 * 2 + buf) * TSLOT;
#pragma unroll
        for (int ks = 0; ks < 2; ks++) {
            unsigned kb = ks * 32;
            unsigned bf[4][2];
            unsigned bo = (unsigned)(warpN * 32 + (lane & 7)) * 80 + kb + (((lane >> 3) & 1) * 16);
#pragma unroll
            for (int ni = 0; ni < 4; ni++) ldsm2(bf[ni], bS + bo + ni * (8 * 80));
            unsigned ao = (unsigned)(warpM * 64 + (lane & 15)) * 80 + kb + ((lane >> 4) * 16);
#pragma unroll
            for (int term = 0; term < 2; term++) {
                unsigned base = term ? bW1 : bW0;
                unsigned a[4][4];
#pragma unroll
                for (int mi = 0; mi < 4; mi++) ldsm4(a[mi], base + ao + mi * (16 * 80));
#pragma unroll
                for (int mi = 0; mi < 4; mi++)
#pragma unroll
                    for (int ni = 0; ni < 4; ni++) mmaf16(acc[mi][ni], a[mi], bf[ni]);
            }
        }
        __syncthreads();
    }

    // epilogue
    int g = lane >> 2, cp2 = (lane & 3) * 2;
    int bimg = n0 >> 10;
    int pix0 = (n0 & 1023) + warpN * 32 + cp2;
#pragma unroll
    for (int mi = 0; mi < 4; mi++) {
#pragma unroll
        for (int h8 = 0; h8 < 2; h8++) {
            int row = m0 + warpM * 64 + mi * 16 + g + h8 * 8;
            if (mode == 0 && row >= 256) {
                int r2 = row - 256;
                if (r2 < 50) {
                    float bias = boff[r2];
                    float* dst = offp + ((size_t)bimg * 50 + r2) * 1024;
#pragma unroll
                    for (int ni = 0; ni < 4; ni++) {
                        float2 v;
                        v.x = acc[mi][ni][h8 * 2 + 0] + bias;
                        v.y = acc[mi][ni][h8 * 2 + 1] + bias;
                        *(float2*)(dst + pix0 + ni * 8) = v;
                    }
                }
            } else {
                float sc = scale[row], sh = shift[row];
                size_t base = ((size_t)bimg * 256 + row) * 1024;
#pragma unroll
                for (int ni = 0; ni < 4; ni++) {
                    float2 v;
                    v.x = fmaf(acc[mi][ni][h8 * 2 + 0], sc, sh);
                    v.y = fmaf(acc[mi][ni][h8 * 2 + 1], sc, sh);
                    size_t o = base + pix0 + ni * 8;
                    if (mode == 0) {
                        v.x = fmaxf(v.x, 0.f); v.y = fmaxf(v.y, 0.f);
                    } else if (mode == 2) {
                        float2 a = *(const float2*)(aux + o);
                        v.x = fmaxf(v.x, 0.f) + a.x; v.y = fmaxf(v.y, 0.f) + a.y;
                    } else {
                        float2 a = *(const float2*)(aux + o);
                        v.x = fmaxf(v.x + a.x, 0.f); v.y = fmaxf(v.y + a.y, 0.f);
                    }
                    *(float2*)(outp + o) = v;
                }
            }
        }
    }
}

// ---------------- launcher ----------------
extern "C" void kernel_launch(void* const* d_in, const int* in_sizes, int n_in,
                              void* d_out, int out_size) {
    const float* x     = (const float*)d_in[0];
    const float* w1    = (const float*)d_in[1];
    const float* w_off = (const float*)d_in[2];
    const float* b_off = (const float*)d_in[3];
    const float* w3    = (const float*)d_in[4];
    const float* w2    = (const float*)d_in[5];
    const float* g1 = (const float*)d_in[6],  *b1 = (const float*)d_in[7];
    const float* m1 = (const float*)d_in[8],  *v1 = (const float*)d_in[9];
    const float* g3 = (const float*)d_in[10], *b3 = (const float*)d_in[11];
    const float* m3 = (const float*)d_in[12], *v3 = (const float*)d_in[13];
    const float* g2 = (const float*)d_in[14], *b2 = (const float*)d_in[15];
    const float* m2 = (const float*)d_in[16], *v2 = (const float*)d_in[17];
    float* out = (float*)d_out;

    cudaFuncSetAttribute(gemm_tc, cudaFuncAttributeMaxDynamicSharedMemorySize, GSMEM);

    __half *S, *wch, *wcl, *w3h, *w3l, *w2h, *w2l;
    float *xT, *gout, *goff, *bn;
    cudaGetSymbolAddress((void**)&S,   g_S);
    cudaGetSymbolAddress((void**)&xT,  g_xT);
    cudaGetSymbolAddress((void**)&gout, g_out);
    cudaGetSymbolAddress((void**)&goff, g_offb);
    cudaGetSymbolAddress((void**)&wch, g_wch);  cudaGetSymbolAddress((void**)&wcl, g_wcl);
    cudaGetSymbolAddress((void**)&w3h, g_w3h);  cudaGetSymbolAddress((void**)&w3l, g_w3l);
    cudaGetSymbolAddress((void**)&w2h, g_w2h);  cudaGetSymbolAddress((void**)&w2l, g_w2l);
    cudaGetSymbolAddress((void**)&bn,  g_bn);

    prep_bn<<<1, 256>>>(g1, b1, m1, v1, g3, b3, m3, v3, g2, b2, m2, v2);
    reorder_w_f16<<<2304, 256>>>(w1, wch, wcl, 256, 9, 0);
    reorder_w_f16<<<1152, 256>>>(w_off, wch, wcl, 50, 9, 256);
    reorder_w_f16<<<6400, 256>>>(w3, w3h, w3l, 256, 25, 0);
    reorder_w_f16<<<2304, 256>>>(w2, w2h, w2l, 256, 9, 0);

    transpose_cl<<<dim3(32, 8, 32), dim3(32, 8)>>>(x, xT);
    im2col_f16<<<36864, 256>>>(xT, S);

    // fused conv1 + offset conv (M=384)
    gemm_tc<<<dim3(3, 256), 256, GSMEM>>>(wch, wcl, S, KCA, 0,
                                          bn, bn + 256, b_off, nullptr, gout, goff);
    // deformable sampling -> S (overwrites; stream-ordered after fused gemm)
    sampler_f16<<<102400, 256>>>(xT, goff, S);
    // deform conv: gout += relu(bn3)
    gemm_tc<<<dim3(2, 256), 256, GSMEM>>>(w3h, w3l, S, KCB, 2,
                                          bn + 512, bn + 768, nullptr, gout, gout, nullptr);

    transpose_cl<<<dim3(32, 8, 32), dim3(32, 8)>>>(gout, xT);
    im2col_f16<<<36864, 256>>>(xT, S);
    // conv2: relu(bn2 + x) -> out
    gemm_tc<<<dim3(2, 256), 256, GSMEM>>>(w2h, w2l, S, KCA, 3,
                                          bn + 1024, bn + 1280, nullptr, x, out, nullptr);
}